// round 1
// baseline (speedup 1.0000x reference)
#include <cuda_runtime.h>
#include <cuda_bf16.h>

#define BB 32
#define CC 32
#define HH 480
#define WW 480
#define LL 120
#define HALF 60
#define PLANE (HH*WW)

// per-batch accumulators: [cnt, sum_y, sum_x] * 32
__device__ float g_acc[BB*3];

__global__ void zero_acc_kernel() {
    int i = threadIdx.x;
    if (i < BB*3) g_acc[i] = 0.0f;
}

// Grid: (blocks_per_batch, BB). Reduces channel-1 plane of each batch.
__global__ void reduce_pos_kernel(const float* __restrict__ in) {
    const int b = blockIdx.y;
    const float* __restrict__ plane = in + (size_t)b * CC * PLANE + (size_t)1 * PLANE;

    float cnt = 0.0f, sy = 0.0f, sx = 0.0f;
    const int stride = gridDim.x * blockDim.x;
    for (int idx = blockIdx.x * blockDim.x + threadIdx.x; idx < PLANE; idx += stride) {
        float v = plane[idx];
        if (v == 1.0f) {
            cnt += 1.0f;
            sy  += (float)(idx / WW);
            sx  += (float)(idx % WW);
        }
    }
    // warp reduce
    #pragma unroll
    for (int o = 16; o > 0; o >>= 1) {
        cnt += __shfl_down_sync(0xffffffffu, cnt, o);
        sy  += __shfl_down_sync(0xffffffffu, sy,  o);
        sx  += __shfl_down_sync(0xffffffffu, sx,  o);
    }
    __shared__ float s[3][32];
    const int lane = threadIdx.x & 31;
    const int w    = threadIdx.x >> 5;
    if (lane == 0) { s[0][w] = cnt; s[1][w] = sy; s[2][w] = sx; }
    __syncthreads();
    if (threadIdx.x == 0) {
        const int nw = blockDim.x >> 5;
        float c = 0.0f, a = 0.0f, d = 0.0f;
        for (int i = 0; i < nw; i++) { c += s[0][i]; a += s[1][i]; d += s[2][i]; }
        // All partial sums are integer-valued and small -> float atomicAdd is exact
        // and therefore order-independent (deterministic).
        if (c != 0.0f) {
            atomicAdd(&g_acc[b*3+0], c);
            atomicAdd(&g_acc[b*3+1], a);
            atomicAdd(&g_acc[b*3+2], d);
        }
    }
}

// Grid: (LL/rows_per_block, CC, BB), block (128, rows_per_block)
__global__ void crop_resize_kernel(const float* __restrict__ in, float* __restrict__ out) {
    const int b = blockIdx.z;
    const int c = blockIdx.y;

    __shared__ int sp[4];   // y_start, ry, x_start, rx
    if (threadIdx.x == 0 && threadIdx.y == 0) {
        float cnt   = g_acc[b*3+0];
        float denom = fmaxf(cnt, 1.0f);
        // rintf = round-half-even, matching jnp.round
        int py = (cnt > 0.0f) ? (int)rintf(g_acc[b*3+1] / denom) : (HH/2);
        int px = (cnt > 0.0f) ? (int)rintf(g_acc[b*3+2] / denom) : (WW/2);
        int ys = max(py - HALF, 0);
        int ye = min(py + HALF, HH);
        int xs = max(px - HALF, 0);
        int xe = min(px + HALF, WW);
        sp[0] = ys; sp[1] = ye - ys; sp[2] = xs; sp[3] = xe - xs;
    }
    __syncthreads();

    const int ox = threadIdx.x;
    const int oy = blockIdx.x * blockDim.y + threadIdx.y;
    if (ox >= LL || oy >= LL) return;

    const int y_start = sp[0], ry = sp[1], x_start = sp[2], rx = sp[3];

    float sy = fmaxf(((float)oy + 0.5f) * ((float)ry / (float)LL) - 0.5f, 0.0f);
    float sx = fmaxf(((float)ox + 0.5f) * ((float)rx / (float)LL) - 0.5f, 0.0f);
    int y0 = (int)sy;                 // sy >= 0 -> trunc == floor
    int x0 = (int)sx;
    int y1 = min(y0 + 1, ry - 1);
    int x1 = min(x0 + 1, rx - 1);
    float wy = sy - (float)y0;
    float wx = sx - (float)x0;

    const float* __restrict__ img = in + (size_t)(b * CC + c) * PLANE;
    const int ra0 = (y_start + y0) * WW;
    const int ra1 = (y_start + y1) * WW;
    const int ca0 = x_start + x0;
    const int ca1 = x_start + x1;

    float v00 = img[ra0 + ca0];
    float v01 = img[ra0 + ca1];
    float v10 = img[ra1 + ca0];
    float v11 = img[ra1 + ca1];

    float top = v00 * (1.0f - wx) + v01 * wx;
    float bot = v10 * (1.0f - wx) + v11 * wx;
    float res = top * (1.0f - wy) + bot * wy;

    out[(((size_t)(b * CC + c)) * LL + oy) * LL + ox] = res;
}

extern "C" void kernel_launch(void* const* d_in, const int* in_sizes, int n_in,
                              void* d_out, int out_size) {
    const float* in = (const float*)d_in[0];
    float* out = (float*)d_out;

    zero_acc_kernel<<<1, 96>>>();

    dim3 rg(30, BB);                 // 960 blocks
    reduce_pos_kernel<<<rg, 256>>>(in);

    dim3 cb(128, 4);                 // 512 threads, covers 4 output rows
    dim3 cg(LL / 4, CC, BB);         // 30 x 32 x 32 = 30720 blocks
    crop_resize_kernel<<<cg, cb>>>(in, out);
}